// round 8
// baseline (speedup 1.0000x reference)
#include <cuda_runtime.h>
#include <cuda_bf16.h>
#include <cstdint>
#include <cstddef>

#define VOCAB   100000
#define EMB     256
#define NS      256
#define BATCH   16384
#define TBLK    128              // rows per block (2 fused tiles of 64)
#define MT      64               // rows per tile
#define NBLK    (BATCH / TBLK)   // 128 blocks -> single wave
#define KPAD    264              // bf16 elems per smem row (256+8 -> conflict-free ldmatrix)

__device__ float g_partials[NBLK];
__device__ int   g_count = 0;

__device__ __forceinline__ float softplus_fast(float x) {
    return fmaxf(x, 0.0f) + __logf(1.0f + __expf(-fabsf(x)));
}

__device__ __forceinline__ uint32_t smem_u32(const void* p) {
    return (uint32_t)__cvta_generic_to_shared(p);
}

__device__ __forceinline__ void ldsm_x4(uint32_t& r0, uint32_t& r1, uint32_t& r2, uint32_t& r3,
                                        uint32_t addr) {
    asm volatile("ldmatrix.sync.aligned.m8n8.x4.shared.b16 {%0,%1,%2,%3}, [%4];"
                 : "=r"(r0), "=r"(r1), "=r"(r2), "=r"(r3) : "r"(addr));
}

__device__ __forceinline__ void mma_bf16(float& c0, float& c1, float& c2, float& c3,
                                         uint32_t a0, uint32_t a1, uint32_t a2, uint32_t a3,
                                         uint32_t b0, uint32_t b1) {
    asm volatile("mma.sync.aligned.m16n8k16.row.col.f32.bf16.bf16.f32 "
                 "{%0,%1,%2,%3}, {%4,%5,%6,%7}, {%8,%9}, {%0,%1,%2,%3};"
                 : "+f"(c0), "+f"(c1), "+f"(c2), "+f"(c3)
                 : "r"(a0), "r"(a1), "r"(a2), "r"(a3), "r"(b0), "r"(b1));
}

__device__ __forceinline__ uint2 pack_bf16x4(float4 v) {
    __nv_bfloat162 p0 = __floats2bfloat162_rn(v.x, v.y);
    __nv_bfloat162 p1 = __floats2bfloat162_rn(v.z, v.w);
    uint2 u;
    u.x = *(uint32_t*)&p0;
    u.y = *(uint32_t*)&p1;
    return u;
}

__device__ __forceinline__ void stcs128(float* p, float4 v) {
    asm volatile("st.global.cs.v4.f32 [%0], {%1,%2,%3,%4};"
                 :: "l"(p), "f"(v.x), "f"(v.y), "f"(v.z), "f"(v.w) : "memory");
}

__global__ void __launch_bounds__(512, 1) w2v_fused(
    const float* __restrict__ emb,
    const float* __restrict__ ncew,
    const float* __restrict__ nceb,
    const int* __restrict__ inputs,
    const int* __restrict__ labels,
    const int* __restrict__ sids,
    float* __restrict__ out)
{
    extern __shared__ unsigned char smem_raw[];
    __nv_bfloat16* sA = (__nv_bfloat16*)smem_raw;             // [2][MT][KPAD]
    __nv_bfloat16* sW = sA + 2 * MT * KPAD;                   // [NS][KPAD]
    float* sCorr = (float*)(sW + (size_t)NS * KPAD);          // [NS]
    int*   sRow  = (int*)(sCorr + NS);                        // [TBLK]
    float* sRed  = (float*)(sRow + TBLK);                     // [16]

    const int tid  = threadIdx.x;
    const int bid  = blockIdx.x;
    const int R0   = bid * TBLK;
    const float INV_LOGV = 1.0f / logf((float)VOCAB + 1.0f);

    if (tid < TBLK) sRow[tid] = inputs[R0 + tid];
    if (tid < NS) {
        int s = sids[tid];
        float p = (logf((float)s + 2.0f) - logf((float)s + 1.0f)) * INV_LOGV;
        sCorr[tid] = nceb[s] - logf((float)NS * p);
    }
    __syncthreads();

    const int warp = tid >> 5;   // 0..15
    const int lane = tid & 31;

    // ================= PHASE 0: ALL gathers + ALL true logits =================
    // Both A tiles: fp32 -> out (streaming), bf16 -> sA
    #pragma unroll
    for (int it = 0; it < TBLK * (EMB / 4) / 512; it++) {   // 16 iters
        int i = it * 512 + tid;
        int r = i >> 6, c4 = i & 63;
        float4 v = __ldg((const float4*)(emb + (size_t)sRow[r] * EMB + c4 * 4));
        stcs128((float*)out + (size_t)(R0 + r) * EMB + c4 * 4, v);
        *(uint2*)(sA + r * KPAD + c4 * 4) = pack_bf16x4(v);
    }
    // W: all 256 sampled rows (shared by both tiles)
    #pragma unroll
    for (int it = 0; it < NS * (EMB / 4) / 512; it++) {     // 32 iters
        int i = it * 512 + tid;
        int r = i >> 6, c4 = i & 63;
        int s = sids[r];
        float4 v = __ldg((const float4*)(ncew + (size_t)s * EMB + c4 * 4));
        *(uint2*)(sW + r * KPAD + c4 * 4) = pack_bf16x4(v);
    }

    // True logits for all 128 rows (8 per warp, two batches of 4)
    float local = 0.0f;
    #pragma unroll
    for (int b = 0; b < 2; b++) {
        int    labv[4];
        float4 tb0[4], tb1[4];
        #pragma unroll
        for (int i = 0; i < 4; i++) {
            int lr = warp * 8 + b * 4 + i;
            labv[i] = labels[R0 + lr];
            const float* wr = ncew + (size_t)labv[i] * EMB + lane * 8;
            tb0[i] = __ldg((const float4*)wr);
            tb1[i] = __ldg((const float4*)(wr + 4));
        }
        #pragma unroll
        for (int i = 0; i < 4; i++) {
            int lr = warp * 8 + b * 4 + i;
            const float* er = emb + (size_t)sRow[lr] * EMB + lane * 8;
            float4 a0 = __ldg((const float4*)er);
            float4 a1 = __ldg((const float4*)(er + 4));
            float s = a0.x * tb0[i].x;
            s = fmaf(a0.y, tb0[i].y, s); s = fmaf(a0.z, tb0[i].z, s); s = fmaf(a0.w, tb0[i].w, s);
            s = fmaf(a1.x, tb1[i].x, s); s = fmaf(a1.y, tb1[i].y, s);
            s = fmaf(a1.z, tb1[i].z, s); s = fmaf(a1.w, tb1[i].w, s);
            #pragma unroll
            for (int o = 16; o; o >>= 1) s += __shfl_xor_sync(0xFFFFFFFFu, s, o);
            if (lane == 0) {
                int lab = labv[i];
                float p = (logf((float)lab + 2.0f) - logf((float)lab + 1.0f)) * INV_LOGV;
                float t = s + nceb[lab] - logf((float)NS * p);
                local += softplus_fast(-t);    // sigmoid_xent(t, 1)
            }
        }
    }
    __syncthreads();   // sA[0..1] + sW ready

    // ======== FUSED 2-TILE MMA: warp owns 32 rows x 32 samples per tile ======
    // 16 warps = 2 row-groups x 8 col-groups. B frags shared across tiles.
    const int rowg = warp & 1;
    const int colg = warp >> 1;
    const int mrow  = rowg * 32;
    const int nbase = colg * 32;

    const int mi = lane >> 3;                    // 0..3
    const int arow  = mrow + (mi & 1) * 8 + (lane & 7);   // + mt*16, + tile*MT
    const int acolb = (mi >> 1) * 8;
    const int bRow  = nbase + (mi >> 1) * 8 + (lane & 7); // + nt2*16
    const int bcolb = (mi & 1) * 8;

    float acc[2][8][4];   // [tile][mt*4+nt][frag]
    #pragma unroll
    for (int t = 0; t < 2; t++)
        #pragma unroll
        for (int n = 0; n < 8; n++) {
            acc[t][n][0] = 0.f; acc[t][n][1] = 0.f; acc[t][n][2] = 0.f; acc[t][n][3] = 0.f;
        }

    #pragma unroll
    for (int k = 0; k < EMB; k += 16) {
        // B: 2 ldsm_x4 -> 4 n8-tiles, shared by both row-tiles
        uint32_t fB[8];
        #pragma unroll
        for (int nt2 = 0; nt2 < 2; nt2++)
            ldsm_x4(fB[4*nt2], fB[4*nt2+1], fB[4*nt2+2], fB[4*nt2+3],
                    smem_u32(sW + (bRow + nt2 * 16) * KPAD + k + bcolb));
        // A: 2 m16-subtiles per tile x 2 tiles = 4 ldsm_x4
        #pragma unroll
        for (int t = 0; t < 2; t++) {
            uint32_t fA[2][4];
            #pragma unroll
            for (int mt = 0; mt < 2; mt++)
                ldsm_x4(fA[mt][0], fA[mt][1], fA[mt][2], fA[mt][3],
                        smem_u32(sA + (t * MT + arow + mt * 16) * KPAD + k + acolb));
            #pragma unroll
            for (int mt = 0; mt < 2; mt++)
                #pragma unroll
                for (int nt = 0; nt < 4; nt++)
                    mma_bf16(acc[t][mt*4+nt][0], acc[t][mt*4+nt][1],
                             acc[t][mt*4+nt][2], acc[t][mt*4+nt][3],
                             fA[mt][0], fA[mt][1], fA[mt][2], fA[mt][3],
                             fB[nt*2], fB[nt*2+1]);
        }
    }

    // ---- Epilogue: sum max(x,0) + log(prod(1+e^-|x|)); 64 factors <= 2^64 ----
    const int q = lane & 3;
    float prod = 1.0f;
    #pragma unroll
    for (int t = 0; t < 2; t++)
        #pragma unroll
        for (int mt = 0; mt < 2; mt++)
            #pragma unroll
            for (int nt = 0; nt < 4; nt++) {
                int c0 = nbase + nt * 8 + q * 2;
                float k0 = sCorr[c0], k1 = sCorr[c0 + 1];
                #pragma unroll
                for (int j = 0; j < 4; j++) {
                    float x = acc[t][mt*4+nt][j] + ((j & 1) ? k1 : k0);
                    local += fmaxf(x, 0.0f);
                    prod *= 1.0f + __expf(-fabsf(x));
                }
            }
    local += __logf(prod);

    // ---- Deterministic block reduction -> per-block partial ----
    #pragma unroll
    for (int o = 16; o; o >>= 1) local += __shfl_xor_sync(0xFFFFFFFFu, local, o);
    if (lane == 0) sRed[warp] = local;
    __syncthreads();
    __shared__ bool sLast;
    if (tid == 0) {
        float v = 0.f;
        #pragma unroll
        for (int w = 0; w < 16; w++) v += sRed[w];
        g_partials[bid] = v;
        __threadfence();
        int old = atomicAdd(&g_count, 1);
        sLast = (old == NBLK - 1);
    }
    __syncthreads();

    // ---- Last block folds all partials into the scalar ----
    if (sLast) {
        __threadfence();
        float v = (tid < NBLK) ? g_partials[tid] : 0.0f;
        #pragma unroll
        for (int o = 16; o; o >>= 1) v += __shfl_xor_sync(0xFFFFFFFFu, v, o);
        if (lane == 0) sRed[warp] = v;
        __syncthreads();
        if (tid == 0) {
            float t = 0.f;
            #pragma unroll
            for (int w = 0; w < 16; w++) t += sRed[w];
            out[(size_t)BATCH * EMB] = t * (1.0f / (float)BATCH);
            g_count = 0;   // reset for next graph replay
        }
    }
}

extern "C" void kernel_launch(void* const* d_in, const int* in_sizes, int n_in,
                              void* d_out, int out_size) {
    const float* emb    = (const float*)d_in[0];
    const float* ncew   = (const float*)d_in[1];
    const float* nceb   = (const float*)d_in[2];
    const int*   inputs = (const int*)d_in[3];
    const int*   labels = (const int*)d_in[4];
    const int*   sids   = (const int*)d_in[5];
    float* out = (float*)d_out;

    size_t smem = (size_t)(2 * MT + NS) * KPAD * sizeof(__nv_bfloat16)
                + (size_t)NS * sizeof(float)
                + (size_t)TBLK * sizeof(int)
                + 16 * sizeof(float);
    cudaFuncSetAttribute(w2v_fused, cudaFuncAttributeMaxDynamicSharedMemorySize, (int)smem);
    w2v_fused<<<NBLK, 512, smem>>>(emb, ncew, nceb, inputs, labels, sids, out);
}

// round 9
// speedup vs baseline: 1.0204x; 1.0204x over previous
#include <cuda_runtime.h>
#include <cuda_bf16.h>
#include <cstdint>
#include <cstddef>

#define VOCAB   100000
#define EMB     256
#define NS      256
#define BATCH   16384
#define TBLK    128              // rows per block (2 tiles of 64)
#define MT      64               // rows per tile
#define NBLK    (BATCH / TBLK)   // 128 blocks -> single wave on 148 SMs
#define KPAD    264              // bf16 elems per smem row (256+8 -> conflict-free ldmatrix)

__device__ float g_partials[NBLK];
__device__ int   g_count = 0;

__device__ __forceinline__ float softplus_fast(float x) {
    return fmaxf(x, 0.0f) + __logf(1.0f + __expf(-fabsf(x)));
}

__device__ __forceinline__ uint32_t smem_u32(const void* p) {
    return (uint32_t)__cvta_generic_to_shared(p);
}

__device__ __forceinline__ void ldsm_x4(uint32_t& r0, uint32_t& r1, uint32_t& r2, uint32_t& r3,
                                        uint32_t addr) {
    asm volatile("ldmatrix.sync.aligned.m8n8.x4.shared.b16 {%0,%1,%2,%3}, [%4];"
                 : "=r"(r0), "=r"(r1), "=r"(r2), "=r"(r3) : "r"(addr));
}

__device__ __forceinline__ void mma_bf16(float& c0, float& c1, float& c2, float& c3,
                                         uint32_t a0, uint32_t a1, uint32_t a2, uint32_t a3,
                                         uint32_t b0, uint32_t b1) {
    asm volatile("mma.sync.aligned.m16n8k16.row.col.f32.bf16.bf16.f32 "
                 "{%0,%1,%2,%3}, {%4,%5,%6,%7}, {%8,%9}, {%0,%1,%2,%3};"
                 : "+f"(c0), "+f"(c1), "+f"(c2), "+f"(c3)
                 : "r"(a0), "r"(a1), "r"(a2), "r"(a3), "r"(b0), "r"(b1));
}

__device__ __forceinline__ uint2 pack_bf16x4(float4 v) {
    __nv_bfloat162 p0 = __floats2bfloat162_rn(v.x, v.y);
    __nv_bfloat162 p1 = __floats2bfloat162_rn(v.z, v.w);
    uint2 u;
    u.x = *(uint32_t*)&p0;
    u.y = *(uint32_t*)&p1;
    return u;
}

__device__ __forceinline__ void stcs128(float* p, float4 v) {
    asm volatile("st.global.cs.v4.f32 [%0], {%1,%2,%3,%4};"
                 :: "l"(p), "f"(v.x), "f"(v.y), "f"(v.z), "f"(v.w) : "memory");
}

__global__ void __launch_bounds__(512, 1) w2v_fused(
    const float* __restrict__ emb,
    const float* __restrict__ ncew,
    const float* __restrict__ nceb,
    const int* __restrict__ inputs,
    const int* __restrict__ labels,
    const int* __restrict__ sids,
    float* __restrict__ out)
{
    extern __shared__ unsigned char smem_raw[];
    __nv_bfloat16* sA = (__nv_bfloat16*)smem_raw;             // [2][MT][KPAD]
    __nv_bfloat16* sW = sA + 2 * MT * KPAD;                   // [NS][KPAD]
    float* sCorr = (float*)(sW + (size_t)NS * KPAD);          // [NS]
    int*   sRow  = (int*)(sCorr + NS);                        // [TBLK]
    float* sRed  = (float*)(sRow + TBLK);                     // [16]

    const int tid  = threadIdx.x;
    const int bid  = blockIdx.x;
    const int R0   = bid * TBLK;
    const float INV_LOGV = 1.0f / logf((float)VOCAB + 1.0f);

    if (tid < TBLK) sRow[tid] = inputs[R0 + tid];
    if (tid < NS) {
        int s = sids[tid];
        float p = (logf((float)s + 2.0f) - logf((float)s + 1.0f)) * INV_LOGV;
        sCorr[tid] = nceb[s] - logf((float)NS * p);
    }
    __syncthreads();

    const int warp = tid >> 5;   // 0..15
    const int lane = tid & 31;

    // ================= PHASE 0: gathers (tile 0 + W) + all true logits =======
    #pragma unroll
    for (int it = 0; it < MT * (EMB / 4) / 512; it++) {     // 8 iters
        int i = it * 512 + tid;
        int r = i >> 6, c4 = i & 63;
        float4 v = __ldg((const float4*)(emb + (size_t)sRow[r] * EMB + c4 * 4));
        stcs128((float*)out + (size_t)(R0 + r) * EMB + c4 * 4, v);
        *(uint2*)(sA + r * KPAD + c4 * 4) = pack_bf16x4(v);
    }
    #pragma unroll
    for (int it = 0; it < NS * (EMB / 4) / 512; it++) {     // 32 iters
        int i = it * 512 + tid;
        int r = i >> 6, c4 = i & 63;
        int s = sids[r];
        float4 v = __ldg((const float4*)(ncew + (size_t)s * EMB + c4 * 4));
        *(uint2*)(sW + r * KPAD + c4 * 4) = pack_bf16x4(v);
    }

    // True logits for ALL 128 rows (8 per warp, two batches of 4)
    float local = 0.0f;
    #pragma unroll
    for (int b = 0; b < 2; b++) {
        int    labv[4];
        float4 tb0[4], tb1[4];
        #pragma unroll
        for (int i = 0; i < 4; i++) {
            int lr = warp * 8 + b * 4 + i;
            labv[i] = labels[R0 + lr];
            const float* wr = ncew + (size_t)labv[i] * EMB + lane * 8;
            tb0[i] = __ldg((const float4*)wr);
            tb1[i] = __ldg((const float4*)(wr + 4));
        }
        #pragma unroll
        for (int i = 0; i < 4; i++) {
            int lr = warp * 8 + b * 4 + i;
            const float* er = emb + (size_t)sRow[lr] * EMB + lane * 8;
            float4 a0 = __ldg((const float4*)er);
            float4 a1 = __ldg((const float4*)(er + 4));
            float s = a0.x * tb0[i].x;
            s = fmaf(a0.y, tb0[i].y, s); s = fmaf(a0.z, tb0[i].z, s); s = fmaf(a0.w, tb0[i].w, s);
            s = fmaf(a1.x, tb1[i].x, s); s = fmaf(a1.y, tb1[i].y, s);
            s = fmaf(a1.z, tb1[i].z, s); s = fmaf(a1.w, tb1[i].w, s);
            #pragma unroll
            for (int o = 16; o; o >>= 1) s += __shfl_xor_sync(0xFFFFFFFFu, s, o);
            if (lane == 0) {
                int lab = labv[i];
                float p = (logf((float)lab + 2.0f) - logf((float)lab + 1.0f)) * INV_LOGV;
                float t = s + nceb[lab] - logf((float)NS * p);
                local += softplus_fast(-t);    // sigmoid_xent(t, 1)
            }
        }
    }
    __syncthreads();   // sA[0] + sW ready

    // ================= TILE LOOP (pipelined, 32x32 warp tiles) ===============
    // 16 warps = 2 row-groups x 8 col-groups; per k-step 2 A + 2 B ldsm_x4.
    const int rowg = warp & 1;
    const int colg = warp >> 1;
    const int mrow  = rowg * 32;
    const int nbase = colg * 32;
    const int mi = lane >> 3;                    // 0..3
    const int arow  = mrow + (mi & 1) * 8 + (lane & 7);   // + mt*16
    const int acolb = (mi >> 1) * 8;
    const int bRow  = nbase + (mi >> 1) * 8 + (lane & 7); // + nt2*16
    const int bcolb = (mi & 1) * 8;
    const int q = lane & 3;

    // Stage registers for tile-1 embed rows: LDGs issue now, consumed after
    // tile-0's MMA — latency fully hidden under compute.
    float4 st[8];
    #pragma unroll
    for (int it = 0; it < 8; it++) {
        int i = it * 512 + tid;
        int r = i >> 6, c4 = i & 63;
        st[it] = __ldg((const float4*)(emb + (size_t)sRow[MT + r] * EMB + c4 * 4));
    }

    #pragma unroll
    for (int t = 0; t < 2; t++) {
        const __nv_bfloat16* sAt = sA + t * MT * KPAD;

        float acc[8][4];   // [mt*4+nt][frag]
        #pragma unroll
        for (int n = 0; n < 8; n++) {
            acc[n][0] = 0.f; acc[n][1] = 0.f; acc[n][2] = 0.f; acc[n][3] = 0.f;
        }

        #pragma unroll
        for (int k = 0; k < EMB; k += 16) {
            uint32_t fB[8];
            #pragma unroll
            for (int nt2 = 0; nt2 < 2; nt2++)
                ldsm_x4(fB[4*nt2], fB[4*nt2+1], fB[4*nt2+2], fB[4*nt2+3],
                        smem_u32(sW + (bRow + nt2 * 16) * KPAD + k + bcolb));
            #pragma unroll
            for (int mt = 0; mt < 2; mt++) {
                uint32_t a0, a1, a2, a3;
                ldsm_x4(a0, a1, a2, a3,
                        smem_u32(sAt + (arow + mt * 16) * KPAD + k + acolb));
                #pragma unroll
                for (int nt = 0; nt < 4; nt++)
                    mma_bf16(acc[mt*4+nt][0], acc[mt*4+nt][1],
                             acc[mt*4+nt][2], acc[mt*4+nt][3],
                             a0, a1, a2, a3, fB[nt*2], fB[nt*2+1]);
            }
        }

        // Epilogue: sum max(x,0) + log(prod(1+e^-|x|)) — one __logf per tile
        float prod = 1.0f;
        #pragma unroll
        for (int mt = 0; mt < 2; mt++)
            #pragma unroll
            for (int nt = 0; nt < 4; nt++) {
                int c0 = nbase + nt * 8 + q * 2;
                float k0 = sCorr[c0], k1 = sCorr[c0 + 1];
                #pragma unroll
                for (int j = 0; j < 4; j++) {
                    float x = acc[mt*4+nt][j] + ((j & 1) ? k1 : k0);
                    local += fmaxf(x, 0.0f);
                    prod *= 1.0f + __expf(-fabsf(x));
                }
            }
        local += __logf(prod);

        if (t == 0) {
            // Drain stage: fp32 -> out (streaming), bf16 -> sA[1]
            #pragma unroll
            for (int it = 0; it < 8; it++) {
                int i = it * 512 + tid;
                int r = i >> 6, c4 = i & 63;
                stcs128((float*)out + (size_t)(R0 + MT + r) * EMB + c4 * 4, st[it]);
                *(uint2*)(sA + MT * KPAD + r * KPAD + c4 * 4) = pack_bf16x4(st[it]);
            }
            __syncthreads();
        }
    }

    // ---- Deterministic block reduction -> per-block partial ----
    #pragma unroll
    for (int o = 16; o; o >>= 1) local += __shfl_xor_sync(0xFFFFFFFFu, local, o);
    if (lane == 0) sRed[warp] = local;
    __syncthreads();
    __shared__ bool sLast;
    if (tid == 0) {
        float v = 0.f;
        #pragma unroll
        for (int w = 0; w < 16; w++) v += sRed[w];
        g_partials[bid] = v;
        __threadfence();
        int old = atomicAdd(&g_count, 1);
        sLast = (old == NBLK - 1);
    }
    __syncthreads();

    // ---- Last block folds all partials into the scalar ----
    if (sLast) {
        __threadfence();
        float v = (tid < NBLK) ? g_partials[tid] : 0.0f;
        #pragma unroll
        for (int o = 16; o; o >>= 1) v += __shfl_xor_sync(0xFFFFFFFFu, v, o);
        if (lane == 0) sRed[warp] = v;
        __syncthreads();
        if (tid == 0) {
            float t = 0.f;
            #pragma unroll
            for (int w = 0; w < 16; w++) t += sRed[w];
            out[(size_t)BATCH * EMB] = t * (1.0f / (float)BATCH);
            g_count = 0;   // reset for next graph replay
        }
    }
}

extern "C" void kernel_launch(void* const* d_in, const int* in_sizes, int n_in,
                              void* d_out, int out_size) {
    const float* emb    = (const float*)d_in[0];
    const float* ncew   = (const float*)d_in[1];
    const float* nceb   = (const float*)d_in[2];
    const int*   inputs = (const int*)d_in[3];
    const int*   labels = (const int*)d_in[4];
    const int*   sids   = (const int*)d_in[5];
    float* out = (float*)d_out;

    size_t smem = (size_t)(2 * MT + NS) * KPAD * sizeof(__nv_bfloat16)
                + (size_t)NS * sizeof(float)
                + (size_t)TBLK * sizeof(int)
                + 16 * sizeof(float);
    cudaFuncSetAttribute(w2v_fused, cudaFuncAttributeMaxDynamicSharedMemorySize, (int)smem);
    w2v_fused<<<NBLK, 512, smem>>>(emb, ncew, nceb, inputs, labels, sids, out);
}